// round 13
// baseline (speedup 1.0000x reference)
#include <cuda_runtime.h>
#include <math.h>

#define IMG    512
#define IMG2   (IMG * IMG)        // 262144 elements per image
#define NBATCH 16
#define NTEN   (NBATCH * IMG2)    // 4194304 per tensor
#define NTOT   (2 * NTEN)         // 8388608 both tensors
#define BMP_WORDS 131080          // ceil((NTEN+1)/32) = 131073, padded
#define FULLMASK 0xffffffffu
#define SIGNBIT  0x80000000
#define PROP_SMEM (2 * 2 * 32 * 32 * 16)   // shTop+shBot, [2][32][32] float4 = 65536 B

// ---------------- device scratch (static, no allocation) ----------------
__device__ float    g_buf[2][NTOT];       // ping-pong label buffers (pred | target)
__device__ unsigned g_bmp[2][BMP_WORDS];  // uniqueness bitmaps
__device__ float    g_pnum[512];          // per (batch,chunk) partial sum p*t
__device__ float    g_pden[512];          // per (batch,chunk) partial sum p^2+t^2
__device__ int      g_maxbits[2];         // float-as-int global max of p, t (values >= 0)
__device__ int      g_cnt[2];             // unique counts

// ---------------- helpers ----------------
// 3-input max in signed-int domain (DPX). For active labels (positive float
// bits) int order == float order; sentinel (negative) inputs always lose.
__device__ __forceinline__ float max3f(float a, float b, float c) {
    return __int_as_float(__vimax3_s32(__float_as_int(a),
                                       __float_as_int(b),
                                       __float_as_int(c)));
}
// apply invariant mask from the old value's sign bit: one LOP3.
__device__ __forceinline__ float sgn_or(float h, float a_old) {
    return __int_as_float(__float_as_int(h) |
                          (__float_as_int(a_old) & SIGNBIT));
}

// ---------------- init: clear scratch ----------------
__global__ void init_kernel() {
    int i = blockIdx.x * blockDim.x + threadIdx.x;
    int stride = gridDim.x * blockDim.x;
    for (int w = i; w < BMP_WORDS; w += stride) {
        g_bmp[0][w] = 0u;
        g_bmp[1][w] = 0u;
    }
    if (i < 512) { g_pnum[i] = 0.f; g_pden[i] = 0.f; }
    if (i < 2)   { g_maxbits[i] = 0; g_cnt[i] = 0; }
}

// ---------------- pass 1: dice partial sums + global maxes ----------------
__global__ void __launch_bounds__(256) reduce_kernel(const float* __restrict__ p,
                                                     const float* __restrict__ t) {
    const int b = blockIdx.y, c = blockIdx.x, tid = threadIdx.x;
    const float4* p4 = reinterpret_cast<const float4*>(p + (size_t)b * IMG2) + c * 2048;
    const float4* t4 = reinterpret_cast<const float4*>(t + (size_t)b * IMG2) + c * 2048;
    float s1 = 0.f, s2 = 0.f, mp = 0.f, mt = 0.f;
#pragma unroll
    for (int k = 0; k < 8; k++) {
        float4 a = p4[k * 256 + tid];
        float4 d = t4[k * 256 + tid];
        s1 += a.x * d.x + a.y * d.y + a.z * d.z + a.w * d.w;
        s2 += a.x * a.x + a.y * a.y + a.z * a.z + a.w * a.w;
        s2 += d.x * d.x + d.y * d.y + d.z * d.z + d.w * d.w;
        mp = fmaxf(mp, fmaxf(fmaxf(a.x, a.y), fmaxf(a.z, a.w)));
        mt = fmaxf(mt, fmaxf(fmaxf(d.x, d.y), fmaxf(d.z, d.w)));
    }
#pragma unroll
    for (int o = 16; o; o >>= 1) {
        s1 += __shfl_down_sync(FULLMASK, s1, o);
        s2 += __shfl_down_sync(FULLMASK, s2, o);
        mp = fmaxf(mp, __shfl_down_sync(FULLMASK, mp, o));
        mt = fmaxf(mt, __shfl_down_sync(FULLMASK, mt, o));
    }
    __shared__ float sh1[8], sh2[8], shm[8], sht[8];
    if ((tid & 31) == 0) {
        int w = tid >> 5;
        sh1[w] = s1; sh2[w] = s2; shm[w] = mp; sht[w] = mt;
    }
    __syncthreads();
    if (tid == 0) {
        float a1 = sh1[0], a2 = sh2[0], m1 = shm[0], m2 = sht[0];
        for (int w = 1; w < 8; w++) {
            a1 += sh1[w]; a2 += sh2[w];
            m1 = fmaxf(m1, shm[w]); m2 = fmaxf(m2, sht[w]);
        }
        g_pnum[b * 32 + c] = a1;
        g_pden[b * 32 + c] = a2;
        atomicMax(&g_maxbits[0], __float_as_int(m1));  // vals >= 0: int order == float order
        atomicMax(&g_maxbits[1], __float_as_int(m2));
    }
}

// ---------------- pass 2: build seed arrays ----------------
// active: label idx+1 (exact fp32); masked: -0.0f sentinel (sign bit = mask)
__global__ void __launch_bounds__(256) seed_kernel(const float* __restrict__ p,
                                                   const float* __restrict__ t) {
    int i = blockIdx.x * blockDim.x + threadIdx.x;   // float4 index, < NTEN/4
    float thp = 0.5f * __int_as_float(g_maxbits[0]);
    float tht = 0.5f * __int_as_float(g_maxbits[1]);
    const float neg0 = __int_as_float(SIGNBIT);
    int base = 4 * i;
    float4 a = reinterpret_cast<const float4*>(p)[i];
    float4 s;
    s.x = (a.x > thp) ? (float)(base + 1) : neg0;
    s.y = (a.y > thp) ? (float)(base + 2) : neg0;
    s.z = (a.z > thp) ? (float)(base + 3) : neg0;
    s.w = (a.w > thp) ? (float)(base + 4) : neg0;
    reinterpret_cast<float4*>(g_buf[0])[i] = s;
    float4 d = reinterpret_cast<const float4*>(t)[i];
    s.x = (d.x > tht) ? (float)(base + 1) : neg0;
    s.y = (d.y > tht) ? (float)(base + 2) : neg0;
    s.z = (d.z > tht) ? (float)(base + 3) : neg0;
    s.w = (d.w > tht) ? (float)(base + 4) : neg0;
    reinterpret_cast<float4*>(g_buf[0] + NTEN)[i] = s;
}

// ---------------- fused propagation: 8 masked 3x3 max-pool iterations ----------------
// Register tile 128x96 (R11 geometry, proven); valid output = tile minus
// margin 8 on image-interior sides. 32 strips of 3 rows; warp w (0..15) owns
// strip w (rows 3w..3w+2) AND strip w+16 (rows 48+3w..): TWO independent
// 3-row dependency chains per warp at R11's register budget (24 data regs),
// so strip B's DPX/LOP3 hides strip A's LDS/SHFL latency (and vice versa);
// each strip's middle row needs no halo and issues before the LDS lands.
// Sentinel masking (negative = masked, sign invariant, one LOP3). Halos via
// dynamic smem indexed by absolute strip id (strips 15<->16 link in-block);
// parity double-buffered, one __syncthreads/iter. Lane-edge clamps via FMUL
// by 0/1 on the FMA pipe.
__device__ __forceinline__ float4 hrow(const float4 v, const float4 aold,
                                       float eL, float eR) {
    float vl = __shfl_up_sync(FULLMASK,  v.w, 1) * eL;
    float vr = __shfl_down_sync(FULLMASK, v.x, 1) * eR;
    float4 o;
    o.x = sgn_or(max3f(vl,  v.x, v.y), aold.x);
    o.y = sgn_or(max3f(v.x, v.y, v.z), aold.y);
    o.z = sgn_or(max3f(v.y, v.z, v.w), aold.z);
    o.w = sgn_or(max3f(v.z, v.w, vr),  aold.w);
    return o;
}
__device__ __forceinline__ float4 vmax3(const float4 a, const float4 b, const float4 c) {
    return make_float4(max3f(a.x, b.x, c.x), max3f(a.y, b.y, c.y),
                       max3f(a.z, b.z, c.z), max3f(a.w, b.w, c.w));
}

__global__ void __launch_bounds__(512, 2) prop8_kernel(int src) {
    const float* __restrict__ in  = g_buf[src];
    float*       __restrict__ out = g_buf[src ^ 1];
    const int img = blockIdx.z;
    const int X0 = min((int)blockIdx.x * 112, 384);   // 5 x-tiles
    const int Y0 = min((int)blockIdx.y * 80,  416);   // 7 y-tiles
    const int w = threadIdx.x >> 5, l = threadIdx.x & 31;
    const int gx  = X0 + 4 * l;
    const int gyA = Y0 + 3 * w;        // strip w       (rows 3w..3w+2)
    const int gyB = Y0 + 48 + 3 * w;   // strip w+16
    const float* base = in + (size_t)img * IMG2;

    float4 A0 = *reinterpret_cast<const float4*>(base + (gyA + 0) * IMG + gx);
    float4 A1 = *reinterpret_cast<const float4*>(base + (gyA + 1) * IMG + gx);
    float4 A2 = *reinterpret_cast<const float4*>(base + (gyA + 2) * IMG + gx);
    float4 B0 = *reinterpret_cast<const float4*>(base + (gyB + 0) * IMG + gx);
    float4 B1 = *reinterpret_cast<const float4*>(base + (gyB + 1) * IMG + gx);
    float4 B2 = *reinterpret_cast<const float4*>(base + (gyB + 2) * IMG + gx);

    const float eL = (l == 0)  ? 0.f : 1.f;   // tile x-edge clamp
    const float eR = (l == 31) ? 0.f : 1.f;

    extern __shared__ float4 sh[];
    float4* shTop = sh;                  // [2][32][32]: strip s top row (3s)
    float4* shBot = sh + 2 * 32 * 32;    // [2][32][32]: strip s bottom row (3s+2)
#define SIDX(p, s) (((p) * 32 + (s)) * 32 + l)
    const float4 s4 = make_float4(__int_as_float(SIGNBIT), __int_as_float(SIGNBIT),
                                  __int_as_float(SIGNBIT), __int_as_float(SIGNBIT));

#pragma unroll
    for (int i = 0; i < 8; i++) {
        const int p = i & 1;
        shTop[SIDX(p, w)]      = A0;
        shBot[SIDX(p, w)]      = A2;
        shTop[SIDX(p, w + 16)] = B0;
        shBot[SIDX(p, w + 16)] = B2;
        __syncthreads();
        // halo loads issued early; middle rows (halo-free) fill the latency
        float4 aTA = (w > 0)  ? shBot[SIDX(p, w - 1)]  : s4;  // sentinel @ tile top
        float4 aBA = shTop[SIDX(p, w + 1)];                   // w=15 -> strip 16 (in-block)
        float4 aTB = shBot[SIDX(p, w + 15)];                  // in-block
        float4 aBB = (w < 15) ? shTop[SIDX(p, w + 17)] : s4;  // sentinel @ tile bottom
        // halo-free middle rows first (independent of LDS results)
        float4 vA1 = vmax3(A0, A1, A2);
        float4 vB1 = vmax3(B0, B1, B2);
        // halo-dependent rows
        float4 vA0 = vmax3(aTA, A0, A1);
        float4 vA2 = vmax3(A1,  A2, aBA);
        float4 vB0 = vmax3(aTB, B0, B1);
        float4 vB2 = vmax3(B1,  B2, aBB);
        // horizontal+mask, A/B interleaved: one chain's DPX/LOP3 hides the
        // other chain's shuffle latency
        A0 = hrow(vA0, A0, eL, eR);
        B0 = hrow(vB0, B0, eL, eR);
        A1 = hrow(vA1, A1, eL, eR);
        B1 = hrow(vB1, B1, eL, eR);
        A2 = hrow(vA2, A2, eL, eR);
        B2 = hrow(vB2, B2, eL, eR);
    }
#undef SIDX

    // store valid (margin-8 or image-edge) region; overlap writes are identical
    const int vx0 = (X0 == 0)   ? 0   : X0 + 8;
    const int vx1 = (X0 == 384) ? 512 : X0 + 120;
    const int vy0 = (Y0 == 0)   ? 0   : Y0 + 8;
    const int vy1 = (Y0 == 416) ? 512 : Y0 + 88;
    float* obase = out + (size_t)img * IMG2;
    if (gx >= vx0 && gx < vx1) {
        if (gyA + 0 >= vy0 && gyA + 0 < vy1)
            *reinterpret_cast<float4*>(obase + (gyA + 0) * IMG + gx) = A0;
        if (gyA + 1 >= vy0 && gyA + 1 < vy1)
            *reinterpret_cast<float4*>(obase + (gyA + 1) * IMG + gx) = A1;
        if (gyA + 2 >= vy0 && gyA + 2 < vy1)
            *reinterpret_cast<float4*>(obase + (gyA + 2) * IMG + gx) = A2;
        if (gyB + 0 >= vy0 && gyB + 0 < vy1)
            *reinterpret_cast<float4*>(obase + (gyB + 0) * IMG + gx) = B0;
        if (gyB + 1 >= vy0 && gyB + 1 < vy1)
            *reinterpret_cast<float4*>(obase + (gyB + 1) * IMG + gx) = B1;
        if (gyB + 2 >= vy0 && gyB + 2 < vy1)
            *reinterpret_cast<float4*>(obase + (gyB + 2) * IMG + gx) = B2;
    }
}

// ---------------- uniqueness: bitmap scatter with fused count ----------------
// Sentinels (negative) clamp to 0 = background, exactly the reference's 0 label.
__global__ void __launch_bounds__(256) scatter_kernel() {
    int i = blockIdx.x * blockDim.x + threadIdx.x;   // float4 index, < NTOT/4
    float4 v = reinterpret_cast<const float4*>(g_buf[1])[i];
    const int which = (i < (NTEN / 4)) ? 0 : 1;      // warp-uniform (NTEN/4 % 32 == 0)
    unsigned* bmp = g_bmp[which];
    unsigned ids[4] = {(unsigned)fmaxf(v.x, 0.f), (unsigned)fmaxf(v.y, 0.f),
                       (unsigned)fmaxf(v.z, 0.f), (unsigned)fmaxf(v.w, 0.f)};
    unsigned prev = 0xffffffffu;
    int cnt = 0;
#pragma unroll
    for (int k = 0; k < 4; k++) {
        unsigned id = ids[k];
        if (id == prev) continue;                 // spatial dedup (labels cluster)
        prev = id;
        unsigned w = id >> 5, m = 1u << (id & 31);
        if (!(bmp[w] & m)) {                      // test first: kills hot-word storms
            unsigned old = atomicOr(&bmp[w], m);
            if (!(old & m)) cnt++;                // this thread flipped the bit
        }
    }
#pragma unroll
    for (int o = 16; o; o >>= 1) cnt += __shfl_down_sync(FULLMASK, cnt, o);
    if ((threadIdx.x & 31) == 0 && cnt)
        atomicAdd(&g_cnt[which], cnt);
}

// ---------------- epilogue ----------------
__global__ void final_kernel(float* __restrict__ out) {
    float acc = 0.f;
    for (int b = 0; b < NBATCH; b++) {
        float num = 0.f, den = 0.f;
        for (int c = 0; c < 32; c++) { num += g_pnum[b * 32 + c]; den += g_pden[b * 32 + c]; }
        acc += 1.0f - (num + 1.0f) / (den + 1.0f);
    }
    float nl = (float)(g_cnt[0] - 1);   // count_unique(labels) - 1
    float nt = (float)g_cnt[1];         // count_unique(target_number)
    float pen = sqrtf(nl / nt);
    if (!isfinite(pen)) pen = (float)NBATCH;
    pen = fminf(fmaxf(pen, 1.0f), (float)NBATCH);
    out[0] = (acc / (float)NBATCH) * pen;
}

// ---------------- launch ----------------
extern "C" void kernel_launch(void* const* d_in, const int* in_sizes, int n_in,
                              void* d_out, int out_size) {
    const float* p = (const float*)d_in[0];
    const float* t = (const float*)d_in[1];
    float* out = (float*)d_out;

    // dynamic smem opt-in (idempotent, host-side, capture-safe)
    cudaFuncSetAttribute(prop8_kernel, cudaFuncAttributeMaxDynamicSharedMemorySize, PROP_SMEM);

    init_kernel<<<512, 256>>>();

    dim3 rgrid(32, 16);
    reduce_kernel<<<rgrid, 256>>>(p, t);

    seed_kernel<<<NTEN / 4 / 256, 256>>>(p, t);

    // 25 launches x 8 fused iterations = 200; ping-pong g_buf[0] <-> g_buf[1]
    dim3 pgrid(5, 7, 32);
    for (int it = 0; it < 25; ++it)
        prop8_kernel<<<pgrid, 512, PROP_SMEM>>>(it & 1);  // result lands in g_buf[1]

    scatter_kernel<<<NTOT / 4 / 256, 256>>>();

    final_kernel<<<1, 1>>>(out);
}

// round 14
// speedup vs baseline: 1.0039x; 1.0039x over previous
#include <cuda_runtime.h>
#include <math.h>

#define IMG    512
#define IMG2   (IMG * IMG)        // 262144 elements per image
#define NBATCH 16
#define NTEN   (NBATCH * IMG2)    // 4194304 per tensor
#define NTOT   (2 * NTEN)         // 8388608 both tensors
#define BMP_WORDS 131080          // ceil((NTEN+1)/32) = 131073, padded
#define FULLMASK 0xffffffffu
#define SIGNBIT  0x80000000
#define PROP_SMEM (2 * 2 * 32 * 32 * 16)   // shTop+shBot, [2][32][32] float4 = 65536 B

// ---------------- device scratch (static, no allocation) ----------------
__device__ float    g_buf[2][NTOT];       // ping-pong label buffers (pred | target)
__device__ unsigned g_bmp[2][BMP_WORDS];  // uniqueness bitmaps
__device__ float    g_pnum[512];          // per (batch,chunk) partial sum p*t
__device__ float    g_pden[512];          // per (batch,chunk) partial sum p^2+t^2
__device__ int      g_maxbits[2];         // float-as-int global max of p, t (values >= 0)
__device__ int      g_cnt[2];             // unique counts

// ---------------- helpers ----------------
// 3-input max in signed-int domain (DPX). For active labels (positive float
// bits) int order == float order; sentinel (negative) inputs always lose.
__device__ __forceinline__ float max3f(float a, float b, float c) {
    return __int_as_float(__vimax3_s32(__float_as_int(a),
                                       __float_as_int(b),
                                       __float_as_int(c)));
}
// apply invariant mask from the old value's sign bit: one LOP3.
__device__ __forceinline__ float sgn_or(float h, float a_old) {
    return __int_as_float(__float_as_int(h) |
                          (__float_as_int(a_old) & SIGNBIT));
}

// ---------------- init: clear scratch ----------------
__global__ void init_kernel() {
    int i = blockIdx.x * blockDim.x + threadIdx.x;
    int stride = gridDim.x * blockDim.x;
    for (int w = i; w < BMP_WORDS; w += stride) {
        g_bmp[0][w] = 0u;
        g_bmp[1][w] = 0u;
    }
    if (i < 512) { g_pnum[i] = 0.f; g_pden[i] = 0.f; }
    if (i < 2)   { g_maxbits[i] = 0; g_cnt[i] = 0; }
}

// ---------------- pass 1: dice partial sums + global maxes ----------------
__global__ void __launch_bounds__(256) reduce_kernel(const float* __restrict__ p,
                                                     const float* __restrict__ t) {
    const int b = blockIdx.y, c = blockIdx.x, tid = threadIdx.x;
    const float4* p4 = reinterpret_cast<const float4*>(p + (size_t)b * IMG2) + c * 2048;
    const float4* t4 = reinterpret_cast<const float4*>(t + (size_t)b * IMG2) + c * 2048;
    float s1 = 0.f, s2 = 0.f, mp = 0.f, mt = 0.f;
#pragma unroll
    for (int k = 0; k < 8; k++) {
        float4 a = p4[k * 256 + tid];
        float4 d = t4[k * 256 + tid];
        s1 += a.x * d.x + a.y * d.y + a.z * d.z + a.w * d.w;
        s2 += a.x * a.x + a.y * a.y + a.z * a.z + a.w * a.w;
        s2 += d.x * d.x + d.y * d.y + d.z * d.z + d.w * d.w;
        mp = fmaxf(mp, fmaxf(fmaxf(a.x, a.y), fmaxf(a.z, a.w)));
        mt = fmaxf(mt, fmaxf(fmaxf(d.x, d.y), fmaxf(d.z, d.w)));
    }
#pragma unroll
    for (int o = 16; o; o >>= 1) {
        s1 += __shfl_down_sync(FULLMASK, s1, o);
        s2 += __shfl_down_sync(FULLMASK, s2, o);
        mp = fmaxf(mp, __shfl_down_sync(FULLMASK, mp, o));
        mt = fmaxf(mt, __shfl_down_sync(FULLMASK, mt, o));
    }
    __shared__ float sh1[8], sh2[8], shm[8], sht[8];
    if ((tid & 31) == 0) {
        int w = tid >> 5;
        sh1[w] = s1; sh2[w] = s2; shm[w] = mp; sht[w] = mt;
    }
    __syncthreads();
    if (tid == 0) {
        float a1 = sh1[0], a2 = sh2[0], m1 = shm[0], m2 = sht[0];
        for (int w = 1; w < 8; w++) {
            a1 += sh1[w]; a2 += sh2[w];
            m1 = fmaxf(m1, shm[w]); m2 = fmaxf(m2, sht[w]);
        }
        g_pnum[b * 32 + c] = a1;
        g_pden[b * 32 + c] = a2;
        atomicMax(&g_maxbits[0], __float_as_int(m1));  // vals >= 0: int order == float order
        atomicMax(&g_maxbits[1], __float_as_int(m2));
    }
}

// ---------------- pass 2: build seed arrays ----------------
// active: label idx+1 (exact fp32); masked: -0.0f sentinel (sign bit = mask)
__global__ void __launch_bounds__(256) seed_kernel(const float* __restrict__ p,
                                                   const float* __restrict__ t) {
    int i = blockIdx.x * blockDim.x + threadIdx.x;   // float4 index, < NTEN/4
    float thp = 0.5f * __int_as_float(g_maxbits[0]);
    float tht = 0.5f * __int_as_float(g_maxbits[1]);
    const float neg0 = __int_as_float(SIGNBIT);
    int base = 4 * i;
    float4 a = reinterpret_cast<const float4*>(p)[i];
    float4 s;
    s.x = (a.x > thp) ? (float)(base + 1) : neg0;
    s.y = (a.y > thp) ? (float)(base + 2) : neg0;
    s.z = (a.z > thp) ? (float)(base + 3) : neg0;
    s.w = (a.w > thp) ? (float)(base + 4) : neg0;
    reinterpret_cast<float4*>(g_buf[0])[i] = s;
    float4 d = reinterpret_cast<const float4*>(t)[i];
    s.x = (d.x > tht) ? (float)(base + 1) : neg0;
    s.y = (d.y > tht) ? (float)(base + 2) : neg0;
    s.z = (d.z > tht) ? (float)(base + 3) : neg0;
    s.w = (d.w > tht) ? (float)(base + 4) : neg0;
    reinterpret_cast<float4*>(g_buf[0] + NTEN)[i] = s;
}

// ---------------- fused propagation: 8 masked 3x3 max-pool iterations ----------------
// Register tile 128x96 (R11 geometry, proven); valid output = tile minus
// margin 8 on image-interior sides. 32 strips of 3 rows; warp w (0..15) owns
// strip w (rows 3w..3w+2) AND strip w+16 (rows 48+3w..): TWO independent
// 3-row dependency chains per warp at R11's register budget (24 data regs),
// so strip B's DPX/LOP3 hides strip A's LDS/SHFL latency (and vice versa);
// each strip's middle row needs no halo and issues before the LDS lands.
// Sentinel masking (negative = masked, sign invariant, one LOP3). Halos via
// dynamic smem indexed by absolute strip id (strips 15<->16 link in-block);
// parity double-buffered, one __syncthreads/iter. Lane-edge clamps via FMUL
// by 0/1 on the FMA pipe.
__device__ __forceinline__ float4 hrow(const float4 v, const float4 aold,
                                       float eL, float eR) {
    float vl = __shfl_up_sync(FULLMASK,  v.w, 1) * eL;
    float vr = __shfl_down_sync(FULLMASK, v.x, 1) * eR;
    float4 o;
    o.x = sgn_or(max3f(vl,  v.x, v.y), aold.x);
    o.y = sgn_or(max3f(v.x, v.y, v.z), aold.y);
    o.z = sgn_or(max3f(v.y, v.z, v.w), aold.z);
    o.w = sgn_or(max3f(v.z, v.w, vr),  aold.w);
    return o;
}
__device__ __forceinline__ float4 vmax3(const float4 a, const float4 b, const float4 c) {
    return make_float4(max3f(a.x, b.x, c.x), max3f(a.y, b.y, c.y),
                       max3f(a.z, b.z, c.z), max3f(a.w, b.w, c.w));
}

__global__ void __launch_bounds__(512, 2) prop8_kernel(int src) {
    const float* __restrict__ in  = g_buf[src];
    float*       __restrict__ out = g_buf[src ^ 1];
    const int img = blockIdx.z;
    const int X0 = min((int)blockIdx.x * 112, 384);   // 5 x-tiles
    const int Y0 = min((int)blockIdx.y * 80,  416);   // 7 y-tiles
    const int w = threadIdx.x >> 5, l = threadIdx.x & 31;
    const int gx  = X0 + 4 * l;
    const int gyA = Y0 + 3 * w;        // strip w       (rows 3w..3w+2)
    const int gyB = Y0 + 48 + 3 * w;   // strip w+16
    const float* base = in + (size_t)img * IMG2;

    float4 A0 = *reinterpret_cast<const float4*>(base + (gyA + 0) * IMG + gx);
    float4 A1 = *reinterpret_cast<const float4*>(base + (gyA + 1) * IMG + gx);
    float4 A2 = *reinterpret_cast<const float4*>(base + (gyA + 2) * IMG + gx);
    float4 B0 = *reinterpret_cast<const float4*>(base + (gyB + 0) * IMG + gx);
    float4 B1 = *reinterpret_cast<const float4*>(base + (gyB + 1) * IMG + gx);
    float4 B2 = *reinterpret_cast<const float4*>(base + (gyB + 2) * IMG + gx);

    const float eL = (l == 0)  ? 0.f : 1.f;   // tile x-edge clamp
    const float eR = (l == 31) ? 0.f : 1.f;

    extern __shared__ float4 sh[];
    float4* shTop = sh;                  // [2][32][32]: strip s top row (3s)
    float4* shBot = sh + 2 * 32 * 32;    // [2][32][32]: strip s bottom row (3s+2)
#define SIDX(p, s) (((p) * 32 + (s)) * 32 + l)
    const float4 s4 = make_float4(__int_as_float(SIGNBIT), __int_as_float(SIGNBIT),
                                  __int_as_float(SIGNBIT), __int_as_float(SIGNBIT));

#pragma unroll
    for (int i = 0; i < 8; i++) {
        const int p = i & 1;
        shTop[SIDX(p, w)]      = A0;
        shBot[SIDX(p, w)]      = A2;
        shTop[SIDX(p, w + 16)] = B0;
        shBot[SIDX(p, w + 16)] = B2;
        __syncthreads();
        // halo loads issued early; middle rows (halo-free) fill the latency
        float4 aTA = (w > 0)  ? shBot[SIDX(p, w - 1)]  : s4;  // sentinel @ tile top
        float4 aBA = shTop[SIDX(p, w + 1)];                   // w=15 -> strip 16 (in-block)
        float4 aTB = shBot[SIDX(p, w + 15)];                  // in-block
        float4 aBB = (w < 15) ? shTop[SIDX(p, w + 17)] : s4;  // sentinel @ tile bottom
        // halo-free middle rows first (independent of LDS results)
        float4 vA1 = vmax3(A0, A1, A2);
        float4 vB1 = vmax3(B0, B1, B2);
        // halo-dependent rows
        float4 vA0 = vmax3(aTA, A0, A1);
        float4 vA2 = vmax3(A1,  A2, aBA);
        float4 vB0 = vmax3(aTB, B0, B1);
        float4 vB2 = vmax3(B1,  B2, aBB);
        // horizontal+mask, A/B interleaved: one chain's DPX/LOP3 hides the
        // other chain's shuffle latency
        A0 = hrow(vA0, A0, eL, eR);
        B0 = hrow(vB0, B0, eL, eR);
        A1 = hrow(vA1, A1, eL, eR);
        B1 = hrow(vB1, B1, eL, eR);
        A2 = hrow(vA2, A2, eL, eR);
        B2 = hrow(vB2, B2, eL, eR);
    }
#undef SIDX

    // store valid (margin-8 or image-edge) region; overlap writes are identical
    const int vx0 = (X0 == 0)   ? 0   : X0 + 8;
    const int vx1 = (X0 == 384) ? 512 : X0 + 120;
    const int vy0 = (Y0 == 0)   ? 0   : Y0 + 8;
    const int vy1 = (Y0 == 416) ? 512 : Y0 + 88;
    float* obase = out + (size_t)img * IMG2;
    if (gx >= vx0 && gx < vx1) {
        if (gyA + 0 >= vy0 && gyA + 0 < vy1)
            *reinterpret_cast<float4*>(obase + (gyA + 0) * IMG + gx) = A0;
        if (gyA + 1 >= vy0 && gyA + 1 < vy1)
            *reinterpret_cast<float4*>(obase + (gyA + 1) * IMG + gx) = A1;
        if (gyA + 2 >= vy0 && gyA + 2 < vy1)
            *reinterpret_cast<float4*>(obase + (gyA + 2) * IMG + gx) = A2;
        if (gyB + 0 >= vy0 && gyB + 0 < vy1)
            *reinterpret_cast<float4*>(obase + (gyB + 0) * IMG + gx) = B0;
        if (gyB + 1 >= vy0 && gyB + 1 < vy1)
            *reinterpret_cast<float4*>(obase + (gyB + 1) * IMG + gx) = B1;
        if (gyB + 2 >= vy0 && gyB + 2 < vy1)
            *reinterpret_cast<float4*>(obase + (gyB + 2) * IMG + gx) = B2;
    }
}

// ---------------- uniqueness: bitmap scatter with fused count ----------------
// Sentinels (negative) clamp to 0 = background, exactly the reference's 0 label.
__global__ void __launch_bounds__(256) scatter_kernel() {
    int i = blockIdx.x * blockDim.x + threadIdx.x;   // float4 index, < NTOT/4
    float4 v = reinterpret_cast<const float4*>(g_buf[1])[i];
    const int which = (i < (NTEN / 4)) ? 0 : 1;      // warp-uniform (NTEN/4 % 32 == 0)
    unsigned* bmp = g_bmp[which];
    unsigned ids[4] = {(unsigned)fmaxf(v.x, 0.f), (unsigned)fmaxf(v.y, 0.f),
                       (unsigned)fmaxf(v.z, 0.f), (unsigned)fmaxf(v.w, 0.f)};
    unsigned prev = 0xffffffffu;
    int cnt = 0;
#pragma unroll
    for (int k = 0; k < 4; k++) {
        unsigned id = ids[k];
        if (id == prev) continue;                 // spatial dedup (labels cluster)
        prev = id;
        unsigned w = id >> 5, m = 1u << (id & 31);
        if (!(bmp[w] & m)) {                      // test first: kills hot-word storms
            unsigned old = atomicOr(&bmp[w], m);
            if (!(old & m)) cnt++;                // this thread flipped the bit
        }
    }
#pragma unroll
    for (int o = 16; o; o >>= 1) cnt += __shfl_down_sync(FULLMASK, cnt, o);
    if ((threadIdx.x & 31) == 0 && cnt)
        atomicAdd(&g_cnt[which], cnt);
}

// ---------------- epilogue ----------------
__global__ void final_kernel(float* __restrict__ out) {
    float acc = 0.f;
    for (int b = 0; b < NBATCH; b++) {
        float num = 0.f, den = 0.f;
        for (int c = 0; c < 32; c++) { num += g_pnum[b * 32 + c]; den += g_pden[b * 32 + c]; }
        acc += 1.0f - (num + 1.0f) / (den + 1.0f);
    }
    float nl = (float)(g_cnt[0] - 1);   // count_unique(labels) - 1
    float nt = (float)g_cnt[1];         // count_unique(target_number)
    float pen = sqrtf(nl / nt);
    if (!isfinite(pen)) pen = (float)NBATCH;
    pen = fminf(fmaxf(pen, 1.0f), (float)NBATCH);
    out[0] = (acc / (float)NBATCH) * pen;
}

// ---------------- launch ----------------
extern "C" void kernel_launch(void* const* d_in, const int* in_sizes, int n_in,
                              void* d_out, int out_size) {
    const float* p = (const float*)d_in[0];
    const float* t = (const float*)d_in[1];
    float* out = (float*)d_out;

    // dynamic smem opt-in (idempotent, host-side, capture-safe)
    cudaFuncSetAttribute(prop8_kernel, cudaFuncAttributeMaxDynamicSharedMemorySize, PROP_SMEM);

    init_kernel<<<512, 256>>>();

    dim3 rgrid(32, 16);
    reduce_kernel<<<rgrid, 256>>>(p, t);

    seed_kernel<<<NTEN / 4 / 256, 256>>>(p, t);

    // 25 launches x 8 fused iterations = 200; ping-pong g_buf[0] <-> g_buf[1]
    dim3 pgrid(5, 7, 32);
    for (int it = 0; it < 25; ++it)
        prop8_kernel<<<pgrid, 512, PROP_SMEM>>>(it & 1);  // result lands in g_buf[1]

    scatter_kernel<<<NTOT / 4 / 256, 256>>>();

    final_kernel<<<1, 1>>>(out);
}

// round 15
// speedup vs baseline: 1.1254x; 1.1210x over previous
#include <cuda_runtime.h>
#include <math.h>

#define IMG    512
#define IMG2   (IMG * IMG)        // 262144 elements per image
#define NBATCH 16
#define NTEN   (NBATCH * IMG2)    // 4194304 per tensor
#define NTOT   (2 * NTEN)         // 8388608 both tensors
#define BMP_WORDS 131080          // ceil((NTEN+1)/32) = 131073, padded
#define FULLMASK 0xffffffffu
#define SIGNBIT  0x80000000

// ---------------- device scratch (static, no allocation) ----------------
__device__ float    g_buf[2][NTOT];       // ping-pong label buffers (pred | target)
__device__ unsigned g_bmp[2][BMP_WORDS];  // uniqueness bitmaps
__device__ float    g_pnum[512];          // per (batch,chunk) partial sum p*t
__device__ float    g_pden[512];          // per (batch,chunk) partial sum p^2+t^2
__device__ int      g_maxbits[2];         // float-as-int global max of p, t (values >= 0)
__device__ int      g_cnt[2];             // unique counts

// ---------------- helpers ----------------
// 3-input max in signed-int domain (DPX). For active labels (positive float
// bits) int order == float order; sentinel (negative) inputs always lose.
__device__ __forceinline__ float max3f(float a, float b, float c) {
    return __int_as_float(__vimax3_s32(__float_as_int(a),
                                       __float_as_int(b),
                                       __float_as_int(c)));
}
// apply invariant mask from the old value's sign bit: one LOP3.
__device__ __forceinline__ float sgn_or(float h, float a_old) {
    return __int_as_float(__float_as_int(h) |
                          (__float_as_int(a_old) & SIGNBIT));
}

// ---------------- init: clear scratch ----------------
__global__ void init_kernel() {
    int i = blockIdx.x * blockDim.x + threadIdx.x;
    int stride = gridDim.x * blockDim.x;
    for (int w = i; w < BMP_WORDS; w += stride) {
        g_bmp[0][w] = 0u;
        g_bmp[1][w] = 0u;
    }
    if (i < 512) { g_pnum[i] = 0.f; g_pden[i] = 0.f; }
    if (i < 2)   { g_maxbits[i] = 0; g_cnt[i] = 0; }
}

// ---------------- pass 1: dice partial sums + global maxes ----------------
__global__ void __launch_bounds__(256) reduce_kernel(const float* __restrict__ p,
                                                     const float* __restrict__ t) {
    const int b = blockIdx.y, c = blockIdx.x, tid = threadIdx.x;
    const float4* p4 = reinterpret_cast<const float4*>(p + (size_t)b * IMG2) + c * 2048;
    const float4* t4 = reinterpret_cast<const float4*>(t + (size_t)b * IMG2) + c * 2048;
    float s1 = 0.f, s2 = 0.f, mp = 0.f, mt = 0.f;
#pragma unroll
    for (int k = 0; k < 8; k++) {
        float4 a = p4[k * 256 + tid];
        float4 d = t4[k * 256 + tid];
        s1 += a.x * d.x + a.y * d.y + a.z * d.z + a.w * d.w;
        s2 += a.x * a.x + a.y * a.y + a.z * a.z + a.w * a.w;
        s2 += d.x * d.x + d.y * d.y + d.z * d.z + d.w * d.w;
        mp = fmaxf(mp, fmaxf(fmaxf(a.x, a.y), fmaxf(a.z, a.w)));
        mt = fmaxf(mt, fmaxf(fmaxf(d.x, d.y), fmaxf(d.z, d.w)));
    }
#pragma unroll
    for (int o = 16; o; o >>= 1) {
        s1 += __shfl_down_sync(FULLMASK, s1, o);
        s2 += __shfl_down_sync(FULLMASK, s2, o);
        mp = fmaxf(mp, __shfl_down_sync(FULLMASK, mp, o));
        mt = fmaxf(mt, __shfl_down_sync(FULLMASK, mt, o));
    }
    __shared__ float sh1[8], sh2[8], shm[8], sht[8];
    if ((tid & 31) == 0) {
        int w = tid >> 5;
        sh1[w] = s1; sh2[w] = s2; shm[w] = mp; sht[w] = mt;
    }
    __syncthreads();
    if (tid == 0) {
        float a1 = sh1[0], a2 = sh2[0], m1 = shm[0], m2 = sht[0];
        for (int w = 1; w < 8; w++) {
            a1 += sh1[w]; a2 += sh2[w];
            m1 = fmaxf(m1, shm[w]); m2 = fmaxf(m2, sht[w]);
        }
        g_pnum[b * 32 + c] = a1;
        g_pden[b * 32 + c] = a2;
        atomicMax(&g_maxbits[0], __float_as_int(m1));  // vals >= 0: int order == float order
        atomicMax(&g_maxbits[1], __float_as_int(m2));
    }
}

// ---------------- pass 2: build seed arrays ----------------
// active: label idx+1 (exact fp32); masked: -0.0f sentinel (sign bit = mask)
__global__ void __launch_bounds__(256) seed_kernel(const float* __restrict__ p,
                                                   const float* __restrict__ t) {
    int i = blockIdx.x * blockDim.x + threadIdx.x;   // float4 index, < NTEN/4
    float thp = 0.5f * __int_as_float(g_maxbits[0]);
    float tht = 0.5f * __int_as_float(g_maxbits[1]);
    const float neg0 = __int_as_float(SIGNBIT);
    int base = 4 * i;
    float4 a = reinterpret_cast<const float4*>(p)[i];
    float4 s;
    s.x = (a.x > thp) ? (float)(base + 1) : neg0;
    s.y = (a.y > thp) ? (float)(base + 2) : neg0;
    s.z = (a.z > thp) ? (float)(base + 3) : neg0;
    s.w = (a.w > thp) ? (float)(base + 4) : neg0;
    reinterpret_cast<float4*>(g_buf[0])[i] = s;
    float4 d = reinterpret_cast<const float4*>(t)[i];
    s.x = (d.x > tht) ? (float)(base + 1) : neg0;
    s.y = (d.y > tht) ? (float)(base + 2) : neg0;
    s.z = (d.z > tht) ? (float)(base + 3) : neg0;
    s.w = (d.w > tht) ? (float)(base + 4) : neg0;
    reinterpret_cast<float4*>(g_buf[0] + NTEN)[i] = s;
}

// ---------------- fused propagation: 8 masked 3x3 max-pool iterations ----------------
// R11 geometry (proven): register tile 128x96; valid output = tile minus
// margin 8 on image-interior sides. Warp w (0..15) owns rows 6w..6w+5; lane l
// owns cols 4l..4l+3 (float4).
// SEPARABLE REORDER: max3x3 = vmax ∘ hmax. The horizontal stage (shuffles +
// DPX) runs FIRST, on values available at iteration start — its 26-cyc shuffle
// latency overlaps the smem store + barrier instead of sitting in the
// post-barrier convoy. The smem halo exchange carries the h-maxed rows, so the
// post-barrier chain is just LDS -> vmax3 -> sign-LOP3 (~37 cyc vs 67).
// Bit-exact: max is separable; sentinel masking (negative = masked, sign
// invariant) re-imposed by one LOP3 from a_old after the vertical stage.
__device__ __forceinline__ float4 hmax(const float4 a, float eL, float eR) {
    float vl = __shfl_up_sync(FULLMASK,  a.w, 1) * eL;
    float vr = __shfl_down_sync(FULLMASK, a.x, 1) * eR;
    float4 h;
    h.x = max3f(vl,  a.x, a.y);
    h.y = max3f(a.x, a.y, a.z);
    h.z = max3f(a.y, a.z, a.w);
    h.w = max3f(a.z, a.w, vr);
    return h;
}
__device__ __forceinline__ float4 vmask(const float4 u, const float4 m, const float4 d,
                                        const float4 aold) {
    float4 o;
    o.x = sgn_or(max3f(u.x, m.x, d.x), aold.x);
    o.y = sgn_or(max3f(u.y, m.y, d.y), aold.y);
    o.z = sgn_or(max3f(u.z, m.z, d.z), aold.z);
    o.w = sgn_or(max3f(u.w, m.w, d.w), aold.w);
    return o;
}

__global__ void __launch_bounds__(512, 2) prop8_kernel(int src) {
    const float* __restrict__ in  = g_buf[src];
    float*       __restrict__ out = g_buf[src ^ 1];
    const int img = blockIdx.z;
    const int X0 = min((int)blockIdx.x * 112, 384);   // 5 x-tiles
    const int Y0 = min((int)blockIdx.y * 80,  416);   // 7 y-tiles {0,80,...,400,416}
    const int w = threadIdx.x >> 5, l = threadIdx.x & 31;
    const int gx  = X0 + 4 * l;
    const int gy0 = Y0 + 6 * w;
    const float* base = in + (size_t)img * IMG2;

    float4 a0 = *reinterpret_cast<const float4*>(base + (gy0 + 0) * IMG + gx);
    float4 a1 = *reinterpret_cast<const float4*>(base + (gy0 + 1) * IMG + gx);
    float4 a2 = *reinterpret_cast<const float4*>(base + (gy0 + 2) * IMG + gx);
    float4 a3 = *reinterpret_cast<const float4*>(base + (gy0 + 3) * IMG + gx);
    float4 a4 = *reinterpret_cast<const float4*>(base + (gy0 + 4) * IMG + gx);
    float4 a5 = *reinterpret_cast<const float4*>(base + (gy0 + 5) * IMG + gx);

    const float eL = (l == 0)  ? 0.f : 1.f;   // tile x-edge clamp
    const float eR = (l == 31) ? 0.f : 1.f;

    __shared__ float4 shTop[2][16][32];   // warp w's H of row 6w
    __shared__ float4 shBot[2][16][32];   // warp w's H of row 6w+5
    const float4 s4 = make_float4(__int_as_float(SIGNBIT), __int_as_float(SIGNBIT),
                                  __int_as_float(SIGNBIT), __int_as_float(SIGNBIT));

#pragma unroll
    for (int i = 0; i < 8; i++) {
        const int p = i & 1;
        // horizontal stage first: shuffle latency overlaps STS + barrier
        float4 H0 = hmax(a0, eL, eR);
        float4 H5 = hmax(a5, eL, eR);
        shTop[p][w][l] = H0;
        shBot[p][w][l] = H5;
        float4 H1 = hmax(a1, eL, eR);
        float4 H2 = hmax(a2, eL, eR);
        float4 H3 = hmax(a3, eL, eR);
        float4 H4 = hmax(a4, eL, eR);
        __syncthreads();
        // post-barrier chain: LDS -> vmax3 -> sign LOP3 only
        float4 HT = (w > 0)  ? shBot[p][w - 1][l] : s4;   // sentinel @ tile top
        float4 HB = (w < 15) ? shTop[p][w + 1][l] : s4;   // sentinel @ tile bottom
        a0 = vmask(HT, H0, H1, a0);
        a1 = vmask(H0, H1, H2, a1);
        a2 = vmask(H1, H2, H3, a2);
        a3 = vmask(H2, H3, H4, a3);
        a4 = vmask(H3, H4, H5, a4);
        a5 = vmask(H4, H5, HB, a5);
    }

    // store valid (margin-8 or image-edge) region; overlap writes are identical
    const int vx0 = (X0 == 0)   ? 0   : X0 + 8;
    const int vx1 = (X0 == 384) ? 512 : X0 + 120;
    const int vy0 = (Y0 == 0)   ? 0   : Y0 + 8;
    const int vy1 = (Y0 == 416) ? 512 : Y0 + 88;
    float* obase = out + (size_t)img * IMG2;
    if (gx >= vx0 && gx < vx1) {
        if (gy0 + 0 >= vy0 && gy0 + 0 < vy1)
            *reinterpret_cast<float4*>(obase + (gy0 + 0) * IMG + gx) = a0;
        if (gy0 + 1 >= vy0 && gy0 + 1 < vy1)
            *reinterpret_cast<float4*>(obase + (gy0 + 1) * IMG + gx) = a1;
        if (gy0 + 2 >= vy0 && gy0 + 2 < vy1)
            *reinterpret_cast<float4*>(obase + (gy0 + 2) * IMG + gx) = a2;
        if (gy0 + 3 >= vy0 && gy0 + 3 < vy1)
            *reinterpret_cast<float4*>(obase + (gy0 + 3) * IMG + gx) = a3;
        if (gy0 + 4 >= vy0 && gy0 + 4 < vy1)
            *reinterpret_cast<float4*>(obase + (gy0 + 4) * IMG + gx) = a4;
        if (gy0 + 5 >= vy0 && gy0 + 5 < vy1)
            *reinterpret_cast<float4*>(obase + (gy0 + 5) * IMG + gx) = a5;
    }
}

// ---------------- uniqueness: bitmap scatter with fused count ----------------
// Sentinels (negative) clamp to 0 = background, exactly the reference's 0 label.
__global__ void __launch_bounds__(256) scatter_kernel() {
    int i = blockIdx.x * blockDim.x + threadIdx.x;   // float4 index, < NTOT/4
    float4 v = reinterpret_cast<const float4*>(g_buf[1])[i];
    const int which = (i < (NTEN / 4)) ? 0 : 1;      // warp-uniform (NTEN/4 % 32 == 0)
    unsigned* bmp = g_bmp[which];
    unsigned ids[4] = {(unsigned)fmaxf(v.x, 0.f), (unsigned)fmaxf(v.y, 0.f),
                       (unsigned)fmaxf(v.z, 0.f), (unsigned)fmaxf(v.w, 0.f)};
    unsigned prev = 0xffffffffu;
    int cnt = 0;
#pragma unroll
    for (int k = 0; k < 4; k++) {
        unsigned id = ids[k];
        if (id == prev) continue;                 // spatial dedup (labels cluster)
        prev = id;
        unsigned w = id >> 5, m = 1u << (id & 31);
        if (!(bmp[w] & m)) {                      // test first: kills hot-word storms
            unsigned old = atomicOr(&bmp[w], m);
            if (!(old & m)) cnt++;                // this thread flipped the bit
        }
    }
#pragma unroll
    for (int o = 16; o; o >>= 1) cnt += __shfl_down_sync(FULLMASK, cnt, o);
    if ((threadIdx.x & 31) == 0 && cnt)
        atomicAdd(&g_cnt[which], cnt);
}

// ---------------- epilogue ----------------
__global__ void final_kernel(float* __restrict__ out) {
    float acc = 0.f;
    for (int b = 0; b < NBATCH; b++) {
        float num = 0.f, den = 0.f;
        for (int c = 0; c < 32; c++) { num += g_pnum[b * 32 + c]; den += g_pden[b * 32 + c]; }
        acc += 1.0f - (num + 1.0f) / (den + 1.0f);
    }
    float nl = (float)(g_cnt[0] - 1);   // count_unique(labels) - 1
    float nt = (float)g_cnt[1];         // count_unique(target_number)
    float pen = sqrtf(nl / nt);
    if (!isfinite(pen)) pen = (float)NBATCH;
    pen = fminf(fmaxf(pen, 1.0f), (float)NBATCH);
    out[0] = (acc / (float)NBATCH) * pen;
}

// ---------------- launch ----------------
extern "C" void kernel_launch(void* const* d_in, const int* in_sizes, int n_in,
                              void* d_out, int out_size) {
    const float* p = (const float*)d_in[0];
    const float* t = (const float*)d_in[1];
    float* out = (float*)d_out;

    init_kernel<<<512, 256>>>();

    dim3 rgrid(32, 16);
    reduce_kernel<<<rgrid, 256>>>(p, t);

    seed_kernel<<<NTEN / 4 / 256, 256>>>(p, t);

    // 25 launches x 8 fused iterations = 200; ping-pong g_buf[0] <-> g_buf[1]
    dim3 pgrid(5, 7, 32);
    for (int it = 0; it < 25; ++it)
        prop8_kernel<<<pgrid, 512>>>(it & 1);     // final result lands in g_buf[1]

    scatter_kernel<<<NTOT / 4 / 256, 256>>>();

    final_kernel<<<1, 1>>>(out);
}

// round 16
// speedup vs baseline: 1.2719x; 1.1302x over previous
#include <cuda_runtime.h>
#include <math.h>

#define IMG    512
#define IMG2   (IMG * IMG)        // 262144 elements per image
#define NBATCH 16
#define NTEN   (NBATCH * IMG2)    // 4194304 per tensor
#define NTOT   (2 * NTEN)         // 8388608 both tensors
#define BMP_WORDS 131080          // ceil((NTEN+1)/32) = 131073, padded
#define FULLMASK 0xffffffffu
#define SIGNBIT  0x80000000

// ---------------- device scratch (static, no allocation) ----------------
__device__ float    g_buf[2][NTOT];       // ping-pong label buffers (pred | target)
__device__ unsigned g_bmp[2][BMP_WORDS];  // uniqueness bitmaps
__device__ float    g_pnum[512];          // per (batch,chunk) partial sum p*t
__device__ float    g_pden[512];          // per (batch,chunk) partial sum p^2+t^2
__device__ int      g_maxbits[2];         // float-as-int global max of p, t (values >= 0)
__device__ int      g_cnt[2];             // unique counts

// ---------------- helpers ----------------
// 3-input max in signed-int domain (DPX). For active labels (positive float
// bits) int order == float order; sentinel (negative) inputs always lose.
__device__ __forceinline__ float max3f(float a, float b, float c) {
    return __int_as_float(__vimax3_s32(__float_as_int(a),
                                       __float_as_int(b),
                                       __float_as_int(c)));
}
// apply invariant mask from the old value's sign bit: one LOP3.
__device__ __forceinline__ float sgn_or(float h, float a_old) {
    return __int_as_float(__float_as_int(h) |
                          (__float_as_int(a_old) & SIGNBIT));
}

// ---------------- init: clear scratch ----------------
__global__ void init_kernel() {
    int i = blockIdx.x * blockDim.x + threadIdx.x;
    int stride = gridDim.x * blockDim.x;
    for (int w = i; w < BMP_WORDS; w += stride) {
        g_bmp[0][w] = 0u;
        g_bmp[1][w] = 0u;
    }
    if (i < 512) { g_pnum[i] = 0.f; g_pden[i] = 0.f; }
    if (i < 2)   { g_maxbits[i] = 0; g_cnt[i] = 0; }
}

// ---------------- pass 1: dice partial sums + global maxes ----------------
__global__ void __launch_bounds__(256) reduce_kernel(const float* __restrict__ p,
                                                     const float* __restrict__ t) {
    const int b = blockIdx.y, c = blockIdx.x, tid = threadIdx.x;
    const float4* p4 = reinterpret_cast<const float4*>(p + (size_t)b * IMG2) + c * 2048;
    const float4* t4 = reinterpret_cast<const float4*>(t + (size_t)b * IMG2) + c * 2048;
    float s1 = 0.f, s2 = 0.f, mp = 0.f, mt = 0.f;
#pragma unroll
    for (int k = 0; k < 8; k++) {
        float4 a = p4[k * 256 + tid];
        float4 d = t4[k * 256 + tid];
        s1 += a.x * d.x + a.y * d.y + a.z * d.z + a.w * d.w;
        s2 += a.x * a.x + a.y * a.y + a.z * a.z + a.w * a.w;
        s2 += d.x * d.x + d.y * d.y + d.z * d.z + d.w * d.w;
        mp = fmaxf(mp, fmaxf(fmaxf(a.x, a.y), fmaxf(a.z, a.w)));
        mt = fmaxf(mt, fmaxf(fmaxf(d.x, d.y), fmaxf(d.z, d.w)));
    }
#pragma unroll
    for (int o = 16; o; o >>= 1) {
        s1 += __shfl_down_sync(FULLMASK, s1, o);
        s2 += __shfl_down_sync(FULLMASK, s2, o);
        mp = fmaxf(mp, __shfl_down_sync(FULLMASK, mp, o));
        mt = fmaxf(mt, __shfl_down_sync(FULLMASK, mt, o));
    }
    __shared__ float sh1[8], sh2[8], shm[8], sht[8];
    if ((tid & 31) == 0) {
        int w = tid >> 5;
        sh1[w] = s1; sh2[w] = s2; shm[w] = mp; sht[w] = mt;
    }
    __syncthreads();
    if (tid == 0) {
        float a1 = sh1[0], a2 = sh2[0], m1 = shm[0], m2 = sht[0];
        for (int w = 1; w < 8; w++) {
            a1 += sh1[w]; a2 += sh2[w];
            m1 = fmaxf(m1, shm[w]); m2 = fmaxf(m2, sht[w]);
        }
        g_pnum[b * 32 + c] = a1;
        g_pden[b * 32 + c] = a2;
        atomicMax(&g_maxbits[0], __float_as_int(m1));  // vals >= 0: int order == float order
        atomicMax(&g_maxbits[1], __float_as_int(m2));
    }
}

// ---------------- fused propagation: 8 masked 3x3 max-pool iterations ----------------
// R11 body (proven): register tile 128x96; valid output = tile minus margin 8
// on image-interior sides. Warp w (0..15) owns rows 6w..6w+5; lane l owns cols
// 4l..4l+3 (float4). Sentinel masking (negative = masked, sign invariant,
// applied by one LOP3); DPX max3. Vertical halo via smem, parity
// double-buffered, 1 syncthreads/iter.
// MODE 0: load labels from g_buf[src], store to g_buf[src^1]
// MODE 1 (first): load p/t tile directly, threshold vs g_maxbits, synthesize
//                 labels in registers (seed kernel fused away)
// MODE 2 (last):  skip global store; scatter valid-region labels into the
//                 uniqueness bitmaps with fused exactly-once count
__device__ __forceinline__ float4 hrow(const float4 v, const float4 aold,
                                       float eL, float eR) {
    float vl = __shfl_up_sync(FULLMASK,  v.w, 1) * eL;
    float vr = __shfl_down_sync(FULLMASK, v.x, 1) * eR;
    float4 o;
    o.x = sgn_or(max3f(vl,  v.x, v.y), aold.x);
    o.y = sgn_or(max3f(v.x, v.y, v.z), aold.y);
    o.z = sgn_or(max3f(v.y, v.z, v.w), aold.z);
    o.w = sgn_or(max3f(v.z, v.w, vr),  aold.w);
    return o;
}
__device__ __forceinline__ float4 vmax3(const float4 a, const float4 b, const float4 c) {
    return make_float4(max3f(a.x, b.x, c.x), max3f(a.y, b.y, c.y),
                       max3f(a.z, b.z, c.z), max3f(a.w, b.w, c.w));
}
__device__ __forceinline__ float4 seed4(const float4 v, float th, float fbase) {
    const float neg0 = __int_as_float(SIGNBIT);
    float4 s;
    s.x = (v.x > th) ? (fbase + 1.f) : neg0;   // fbase+k exact: < 2^23
    s.y = (v.y > th) ? (fbase + 2.f) : neg0;
    s.z = (v.z > th) ? (fbase + 3.f) : neg0;
    s.w = (v.w > th) ? (fbase + 4.f) : neg0;
    return s;
}

template <int MODE>
__global__ void __launch_bounds__(512, 2) prop8_kernel(int src,
                                                       const float* __restrict__ p,
                                                       const float* __restrict__ t) {
    const int img = blockIdx.z;
    const int X0 = min((int)blockIdx.x * 112, 384);   // 5 x-tiles
    const int Y0 = min((int)blockIdx.y * 80,  416);   // 7 y-tiles {0,80,...,400,416}
    const int w = threadIdx.x >> 5, l = threadIdx.x & 31;
    const int gx  = X0 + 4 * l;
    const int gy0 = Y0 + 6 * w;

    float4 a0, a1, a2, a3, a4, a5;
    if (MODE == 1) {
        // fused seed: read source tensor tile, threshold, synthesize labels
        const float* sbase = (img < NBATCH ? p + (size_t)img * IMG2
                                           : t + (size_t)(img - NBATCH) * IMG2);
        const float th = 0.5f * __int_as_float(g_maxbits[img >> 4]);
        const float ibase = (float)((img & 15) * IMG2 + gx);
        a0 = seed4(*reinterpret_cast<const float4*>(sbase + (gy0 + 0) * IMG + gx), th, ibase + (float)((gy0 + 0) * IMG));
        a1 = seed4(*reinterpret_cast<const float4*>(sbase + (gy0 + 1) * IMG + gx), th, ibase + (float)((gy0 + 1) * IMG));
        a2 = seed4(*reinterpret_cast<const float4*>(sbase + (gy0 + 2) * IMG + gx), th, ibase + (float)((gy0 + 2) * IMG));
        a3 = seed4(*reinterpret_cast<const float4*>(sbase + (gy0 + 3) * IMG + gx), th, ibase + (float)((gy0 + 3) * IMG));
        a4 = seed4(*reinterpret_cast<const float4*>(sbase + (gy0 + 4) * IMG + gx), th, ibase + (float)((gy0 + 4) * IMG));
        a5 = seed4(*reinterpret_cast<const float4*>(sbase + (gy0 + 5) * IMG + gx), th, ibase + (float)((gy0 + 5) * IMG));
    } else {
        const float* base = g_buf[src] + (size_t)img * IMG2;
        a0 = *reinterpret_cast<const float4*>(base + (gy0 + 0) * IMG + gx);
        a1 = *reinterpret_cast<const float4*>(base + (gy0 + 1) * IMG + gx);
        a2 = *reinterpret_cast<const float4*>(base + (gy0 + 2) * IMG + gx);
        a3 = *reinterpret_cast<const float4*>(base + (gy0 + 3) * IMG + gx);
        a4 = *reinterpret_cast<const float4*>(base + (gy0 + 4) * IMG + gx);
        a5 = *reinterpret_cast<const float4*>(base + (gy0 + 5) * IMG + gx);
    }

    const float eL = (l == 0)  ? 0.f : 1.f;   // tile x-edge clamp
    const float eR = (l == 31) ? 0.f : 1.f;

    __shared__ float4 shTop[2][16][32];   // warp w's row 6w
    __shared__ float4 shBot[2][16][32];   // warp w's row 6w+5
    const float4 s4 = make_float4(__int_as_float(SIGNBIT), __int_as_float(SIGNBIT),
                                  __int_as_float(SIGNBIT), __int_as_float(SIGNBIT));

#pragma unroll
    for (int i = 0; i < 8; i++) {
        const int pp = i & 1;
        shTop[pp][w][l] = a0;
        shBot[pp][w][l] = a5;
        __syncthreads();
        float4 aT = (w > 0)  ? shBot[pp][w - 1][l] : s4;
        float4 aB = (w < 15) ? shTop[pp][w + 1][l] : s4;
        float4 v0 = vmax3(aT, a0, a1);
        float4 v1 = vmax3(a0, a1, a2);
        float4 v2 = vmax3(a1, a2, a3);
        float4 v3 = vmax3(a2, a3, a4);
        float4 v4 = vmax3(a3, a4, a5);
        float4 v5 = vmax3(a4, a5, aB);
        a0 = hrow(v0, a0, eL, eR);
        a1 = hrow(v1, a1, eL, eR);
        a2 = hrow(v2, a2, eL, eR);
        a3 = hrow(v3, a3, eL, eR);
        a4 = hrow(v4, a4, eL, eR);
        a5 = hrow(v5, a5, eL, eR);
    }

    // valid (margin-8 or image-edge) region
    const int vx0 = (X0 == 0)   ? 0   : X0 + 8;
    const int vx1 = (X0 == 384) ? 512 : X0 + 120;
    const int vy0 = (Y0 == 0)   ? 0   : Y0 + 8;
    const int vy1 = (Y0 == 416) ? 512 : Y0 + 88;
    const bool xok = (gx >= vx0 && gx < vx1);

    if (MODE != 2) {
        float* obase = g_buf[src ^ 1] + (size_t)img * IMG2;
        if (xok) {
            if (gy0 + 0 >= vy0 && gy0 + 0 < vy1)
                *reinterpret_cast<float4*>(obase + (gy0 + 0) * IMG + gx) = a0;
            if (gy0 + 1 >= vy0 && gy0 + 1 < vy1)
                *reinterpret_cast<float4*>(obase + (gy0 + 1) * IMG + gx) = a1;
            if (gy0 + 2 >= vy0 && gy0 + 2 < vy1)
                *reinterpret_cast<float4*>(obase + (gy0 + 2) * IMG + gx) = a2;
            if (gy0 + 3 >= vy0 && gy0 + 3 < vy1)
                *reinterpret_cast<float4*>(obase + (gy0 + 3) * IMG + gx) = a3;
            if (gy0 + 4 >= vy0 && gy0 + 4 < vy1)
                *reinterpret_cast<float4*>(obase + (gy0 + 4) * IMG + gx) = a4;
            if (gy0 + 5 >= vy0 && gy0 + 5 < vy1)
                *reinterpret_cast<float4*>(obase + (gy0 + 5) * IMG + gx) = a5;
        }
    } else {
        // fused scatter + exactly-once unique count (no global store needed:
        // these labels' only consumer is the bitmap). Sentinels clamp to 0 =
        // background. Overlap px may scatter twice: atomicOr return credits
        // each bit exactly once globally. Margin px excluded by guards.
        const int which = img >> 4;
        unsigned* bmp = g_bmp[which];
        int cnt = 0;
        unsigned prev = 0xffffffffu;
        float4 rows[6] = {a0, a1, a2, a3, a4, a5};
#pragma unroll
        for (int r = 0; r < 6; r++) {
            if (xok && (gy0 + r >= vy0) && (gy0 + r < vy1)) {
                float4 v = rows[r];
                unsigned ids[4] = {(unsigned)fmaxf(v.x, 0.f), (unsigned)fmaxf(v.y, 0.f),
                                   (unsigned)fmaxf(v.z, 0.f), (unsigned)fmaxf(v.w, 0.f)};
#pragma unroll
                for (int k = 0; k < 4; k++) {
                    unsigned id = ids[k];
                    if (id == prev) continue;                 // spatial dedup
                    prev = id;
                    unsigned wd = id >> 5, m = 1u << (id & 31);
                    if (!(bmp[wd] & m)) {                     // test first
                        unsigned old = atomicOr(&bmp[wd], m);
                        if (!(old & m)) cnt++;                // flipped the bit
                    }
                }
            }
        }
#pragma unroll
        for (int o = 16; o; o >>= 1) cnt += __shfl_down_sync(FULLMASK, cnt, o);
        if (l == 0 && cnt) atomicAdd(&g_cnt[which], cnt);
    }
}

// ---------------- epilogue ----------------
__global__ void final_kernel(float* __restrict__ out) {
    float acc = 0.f;
    for (int b = 0; b < NBATCH; b++) {
        float num = 0.f, den = 0.f;
        for (int c = 0; c < 32; c++) { num += g_pnum[b * 32 + c]; den += g_pden[b * 32 + c]; }
        acc += 1.0f - (num + 1.0f) / (den + 1.0f);
    }
    float nl = (float)(g_cnt[0] - 1);   // count_unique(labels) - 1
    float nt = (float)g_cnt[1];         // count_unique(target_number)
    float pen = sqrtf(nl / nt);
    if (!isfinite(pen)) pen = (float)NBATCH;
    pen = fminf(fmaxf(pen, 1.0f), (float)NBATCH);
    out[0] = (acc / (float)NBATCH) * pen;
}

// ---------------- launch ----------------
extern "C" void kernel_launch(void* const* d_in, const int* in_sizes, int n_in,
                              void* d_out, int out_size) {
    const float* p = (const float*)d_in[0];
    const float* t = (const float*)d_in[1];
    float* out = (float*)d_out;

    init_kernel<<<512, 256>>>();

    dim3 rgrid(32, 16);
    reduce_kernel<<<rgrid, 256>>>(p, t);

    // 25 prop launches x 8 fused iterations = 200.
    // launch 0: fused seed (reads p/t, writes g_buf[1])
    // launches 1..23: standard ping-pong (src = it&1)
    // launch 24: fused scatter+count (reads g_buf[0], no store)
    dim3 pgrid(5, 7, 32);
    prop8_kernel<1><<<pgrid, 512>>>(0, p, t);
    for (int it = 1; it < 24; ++it)
        prop8_kernel<0><<<pgrid, 512>>>(it & 1, p, t);
    prop8_kernel<2><<<pgrid, 512>>>(0, p, t);

    final_kernel<<<1, 1>>>(out);
}

// round 17
// speedup vs baseline: 1.2986x; 1.0209x over previous
#include <cuda_runtime.h>
#include <math.h>

#define IMG    512
#define IMG2   (IMG * IMG)        // 262144 elements per image
#define NBATCH 16
#define NTEN   (NBATCH * IMG2)    // 4194304 per tensor
#define NTOT   (2 * NTEN)         // 8388608 both tensors
#define BMP_WORDS 131080          // ceil((NTEN+1)/32) = 131073, padded
#define FULLMASK 0xffffffffu
#define SIGNBIT  0x80000000

// ---------------- device scratch (static, no allocation) ----------------
__device__ float    g_buf[2][NTOT];       // ping-pong label buffers (pred | target)
__device__ unsigned g_bmp[2][BMP_WORDS];  // uniqueness bitmaps
__device__ float    g_pnum[512];          // per (batch,chunk) partial sum p*t
__device__ float    g_pden[512];          // per (batch,chunk) partial sum p^2+t^2
__device__ int      g_maxbits[2];         // float-as-int global max of p, t (values >= 0)
__device__ int      g_cnt[2];             // unique counts

// ---------------- helpers ----------------
// 3-input max in signed-int domain (DPX). For active labels (positive float
// bits) int order == float order; sentinel (negative) inputs always lose.
__device__ __forceinline__ float max3f(float a, float b, float c) {
    return __int_as_float(__vimax3_s32(__float_as_int(a),
                                       __float_as_int(b),
                                       __float_as_int(c)));
}
// apply invariant mask from the old value's sign bit: one LOP3.
__device__ __forceinline__ float sgn_or(float h, float a_old) {
    return __int_as_float(__float_as_int(h) |
                          (__float_as_int(a_old) & SIGNBIT));
}

// ---------------- init: clear scratch ----------------
__global__ void init_kernel() {
    int i = blockIdx.x * blockDim.x + threadIdx.x;
    int stride = gridDim.x * blockDim.x;
    for (int w = i; w < BMP_WORDS; w += stride) {
        g_bmp[0][w] = 0u;
        g_bmp[1][w] = 0u;
    }
    if (i < 512) { g_pnum[i] = 0.f; g_pden[i] = 0.f; }
    if (i < 2)   { g_maxbits[i] = 0; g_cnt[i] = 0; }
}

// ---------------- pass 1: dice partial sums + global maxes ----------------
__global__ void __launch_bounds__(256) reduce_kernel(const float* __restrict__ p,
                                                     const float* __restrict__ t) {
    const int b = blockIdx.y, c = blockIdx.x, tid = threadIdx.x;
    const float4* p4 = reinterpret_cast<const float4*>(p + (size_t)b * IMG2) + c * 2048;
    const float4* t4 = reinterpret_cast<const float4*>(t + (size_t)b * IMG2) + c * 2048;
    float s1 = 0.f, s2 = 0.f, mp = 0.f, mt = 0.f;
#pragma unroll
    for (int k = 0; k < 8; k++) {
        float4 a = p4[k * 256 + tid];
        float4 d = t4[k * 256 + tid];
        s1 += a.x * d.x + a.y * d.y + a.z * d.z + a.w * d.w;
        s2 += a.x * a.x + a.y * a.y + a.z * a.z + a.w * a.w;
        s2 += d.x * d.x + d.y * d.y + d.z * d.z + d.w * d.w;
        mp = fmaxf(mp, fmaxf(fmaxf(a.x, a.y), fmaxf(a.z, a.w)));
        mt = fmaxf(mt, fmaxf(fmaxf(d.x, d.y), fmaxf(d.z, d.w)));
    }
#pragma unroll
    for (int o = 16; o; o >>= 1) {
        s1 += __shfl_down_sync(FULLMASK, s1, o);
        s2 += __shfl_down_sync(FULLMASK, s2, o);
        mp = fmaxf(mp, __shfl_down_sync(FULLMASK, mp, o));
        mt = fmaxf(mt, __shfl_down_sync(FULLMASK, mt, o));
    }
    __shared__ float sh1[8], sh2[8], shm[8], sht[8];
    if ((tid & 31) == 0) {
        int w = tid >> 5;
        sh1[w] = s1; sh2[w] = s2; shm[w] = mp; sht[w] = mt;
    }
    __syncthreads();
    if (tid == 0) {
        float a1 = sh1[0], a2 = sh2[0], m1 = shm[0], m2 = sht[0];
        for (int w = 1; w < 8; w++) {
            a1 += sh1[w]; a2 += sh2[w];
            m1 = fmaxf(m1, shm[w]); m2 = fmaxf(m2, sht[w]);
        }
        g_pnum[b * 32 + c] = a1;
        g_pden[b * 32 + c] = a2;
        atomicMax(&g_maxbits[0], __float_as_int(m1));  // vals >= 0: int order == float order
        atomicMax(&g_maxbits[1], __float_as_int(m2));
    }
}

// ---------------- fused propagation: 8 masked 3x3 max-pool iterations ----------------
// R16 structure (proven): register tile 128x96; valid output = tile minus
// margin 8 on image-interior sides. Warp w (0..15) owns rows 6w..6w+5; lane l
// owns cols 4l..4l+3 (float4). Sentinel masking (negative = masked, sign
// invariant, one LOP3); DPX max3. Vertical halo via smem, parity
// double-buffered, 1 syncthreads/iter.
// DEFER_BLOCKING exploit: BAR.SYNC does not block at issue on this arch — the
// warp stalls at the first smem consumer. So the halo-independent work (middle
// vertical maxes + full rows 2,3) runs BEFORE the halo LDS, with a scheduling
// fence pinning the LDS below it: each warp absorbs barrier-arrival skew with
// useful work instead of stalling at an immediately-issued LDS.
// MODE 0: load labels from g_buf[src], store to g_buf[src^1]
// MODE 1 (first): load p/t tile directly, threshold vs g_maxbits, synthesize
//                 labels in registers (seed kernel fused away)
// MODE 2 (last):  skip global store; scatter valid-region labels into the
//                 uniqueness bitmaps with fused exactly-once count
__device__ __forceinline__ float4 hrow(const float4 v, const float4 aold,
                                       float eL, float eR) {
    float vl = __shfl_up_sync(FULLMASK,  v.w, 1) * eL;
    float vr = __shfl_down_sync(FULLMASK, v.x, 1) * eR;
    float4 o;
    o.x = sgn_or(max3f(vl,  v.x, v.y), aold.x);
    o.y = sgn_or(max3f(v.x, v.y, v.z), aold.y);
    o.z = sgn_or(max3f(v.y, v.z, v.w), aold.z);
    o.w = sgn_or(max3f(v.z, v.w, vr),  aold.w);
    return o;
}
__device__ __forceinline__ float4 vmax3(const float4 a, const float4 b, const float4 c) {
    return make_float4(max3f(a.x, b.x, c.x), max3f(a.y, b.y, c.y),
                       max3f(a.z, b.z, c.z), max3f(a.w, b.w, c.w));
}
__device__ __forceinline__ float4 seed4(const float4 v, float th, float fbase) {
    const float neg0 = __int_as_float(SIGNBIT);
    float4 s;
    s.x = (v.x > th) ? (fbase + 1.f) : neg0;   // fbase+k exact: < 2^23
    s.y = (v.y > th) ? (fbase + 2.f) : neg0;
    s.z = (v.z > th) ? (fbase + 3.f) : neg0;
    s.w = (v.w > th) ? (fbase + 4.f) : neg0;
    return s;
}

template <int MODE>
__global__ void __launch_bounds__(512, 2) prop8_kernel(int src,
                                                       const float* __restrict__ p,
                                                       const float* __restrict__ t) {
    const int img = blockIdx.z;
    const int X0 = min((int)blockIdx.x * 112, 384);   // 5 x-tiles
    const int Y0 = min((int)blockIdx.y * 80,  416);   // 7 y-tiles {0,80,...,400,416}
    const int w = threadIdx.x >> 5, l = threadIdx.x & 31;
    const int gx  = X0 + 4 * l;
    const int gy0 = Y0 + 6 * w;

    float4 a0, a1, a2, a3, a4, a5;
    if (MODE == 1) {
        // fused seed: read source tensor tile, threshold, synthesize labels
        const float* sbase = (img < NBATCH ? p + (size_t)img * IMG2
                                           : t + (size_t)(img - NBATCH) * IMG2);
        const float th = 0.5f * __int_as_float(g_maxbits[img >> 4]);
        const float ibase = (float)((img & 15) * IMG2 + gx);
        a0 = seed4(*reinterpret_cast<const float4*>(sbase + (gy0 + 0) * IMG + gx), th, ibase + (float)((gy0 + 0) * IMG));
        a1 = seed4(*reinterpret_cast<const float4*>(sbase + (gy0 + 1) * IMG + gx), th, ibase + (float)((gy0 + 1) * IMG));
        a2 = seed4(*reinterpret_cast<const float4*>(sbase + (gy0 + 2) * IMG + gx), th, ibase + (float)((gy0 + 2) * IMG));
        a3 = seed4(*reinterpret_cast<const float4*>(sbase + (gy0 + 3) * IMG + gx), th, ibase + (float)((gy0 + 3) * IMG));
        a4 = seed4(*reinterpret_cast<const float4*>(sbase + (gy0 + 4) * IMG + gx), th, ibase + (float)((gy0 + 4) * IMG));
        a5 = seed4(*reinterpret_cast<const float4*>(sbase + (gy0 + 5) * IMG + gx), th, ibase + (float)((gy0 + 5) * IMG));
    } else {
        const float* base = g_buf[src] + (size_t)img * IMG2;
        a0 = *reinterpret_cast<const float4*>(base + (gy0 + 0) * IMG + gx);
        a1 = *reinterpret_cast<const float4*>(base + (gy0 + 1) * IMG + gx);
        a2 = *reinterpret_cast<const float4*>(base + (gy0 + 2) * IMG + gx);
        a3 = *reinterpret_cast<const float4*>(base + (gy0 + 3) * IMG + gx);
        a4 = *reinterpret_cast<const float4*>(base + (gy0 + 4) * IMG + gx);
        a5 = *reinterpret_cast<const float4*>(base + (gy0 + 5) * IMG + gx);
    }

    const float eL = (l == 0)  ? 0.f : 1.f;   // tile x-edge clamp
    const float eR = (l == 31) ? 0.f : 1.f;

    __shared__ float4 shTop[2][16][32];   // warp w's row 6w
    __shared__ float4 shBot[2][16][32];   // warp w's row 6w+5
    const float4 s4 = make_float4(__int_as_float(SIGNBIT), __int_as_float(SIGNBIT),
                                  __int_as_float(SIGNBIT), __int_as_float(SIGNBIT));

#pragma unroll
    for (int i = 0; i < 8; i++) {
        const int pp = i & 1;
        shTop[pp][w][l] = a0;
        shBot[pp][w][l] = a5;
        __syncthreads();
        // halo-independent work first (deferred-blocking barrier lets this
        // issue while other warps are still arriving)
        float4 v1 = vmax3(a0, a1, a2);
        float4 v2 = vmax3(a1, a2, a3);
        float4 v3 = vmax3(a2, a3, a4);
        float4 v4 = vmax3(a3, a4, a5);
        // rows 2,3 fully finished (their old values feed nothing below)
        a2 = hrow(v2, a2, eL, eR);
        a3 = hrow(v3, a3, eL, eR);
        // scheduling fence: pin the halo LDS below the independent work so the
        // barrier's deferred block point is reached as late as possible
        asm volatile("" ::: "memory");
        float4 aT = (w > 0)  ? shBot[pp][w - 1][l] : s4;
        float4 aB = (w < 15) ? shTop[pp][w + 1][l] : s4;
        float4 v0 = vmax3(aT, a0, a1);   // old a0,a1 still live
        float4 v5 = vmax3(a4, a5, aB);   // old a4,a5 still live
        a0 = hrow(v0, a0, eL, eR);
        a1 = hrow(v1, a1, eL, eR);
        a4 = hrow(v4, a4, eL, eR);
        a5 = hrow(v5, a5, eL, eR);
    }

    // valid (margin-8 or image-edge) region
    const int vx0 = (X0 == 0)   ? 0   : X0 + 8;
    const int vx1 = (X0 == 384) ? 512 : X0 + 120;
    const int vy0 = (Y0 == 0)   ? 0   : Y0 + 8;
    const int vy1 = (Y0 == 416) ? 512 : Y0 + 88;
    const bool xok = (gx >= vx0 && gx < vx1);

    if (MODE != 2) {
        float* obase = g_buf[src ^ 1] + (size_t)img * IMG2;
        if (xok) {
            if (gy0 + 0 >= vy0 && gy0 + 0 < vy1)
                *reinterpret_cast<float4*>(obase + (gy0 + 0) * IMG + gx) = a0;
            if (gy0 + 1 >= vy0 && gy0 + 1 < vy1)
                *reinterpret_cast<float4*>(obase + (gy0 + 1) * IMG + gx) = a1;
            if (gy0 + 2 >= vy0 && gy0 + 2 < vy1)
                *reinterpret_cast<float4*>(obase + (gy0 + 2) * IMG + gx) = a2;
            if (gy0 + 3 >= vy0 && gy0 + 3 < vy1)
                *reinterpret_cast<float4*>(obase + (gy0 + 3) * IMG + gx) = a3;
            if (gy0 + 4 >= vy0 && gy0 + 4 < vy1)
                *reinterpret_cast<float4*>(obase + (gy0 + 4) * IMG + gx) = a4;
            if (gy0 + 5 >= vy0 && gy0 + 5 < vy1)
                *reinterpret_cast<float4*>(obase + (gy0 + 5) * IMG + gx) = a5;
        }
    } else {
        // fused scatter + exactly-once unique count (no global store needed).
        // Sentinels clamp to 0 = background. atomicOr return credits each bit
        // exactly once globally even with tile overlap; margin px excluded.
        const int which = img >> 4;
        unsigned* bmp = g_bmp[which];
        int cnt = 0;
        unsigned prev = 0xffffffffu;
        float4 rows[6] = {a0, a1, a2, a3, a4, a5};
#pragma unroll
        for (int r = 0; r < 6; r++) {
            if (xok && (gy0 + r >= vy0) && (gy0 + r < vy1)) {
                float4 v = rows[r];
                unsigned ids[4] = {(unsigned)fmaxf(v.x, 0.f), (unsigned)fmaxf(v.y, 0.f),
                                   (unsigned)fmaxf(v.z, 0.f), (unsigned)fmaxf(v.w, 0.f)};
#pragma unroll
                for (int k = 0; k < 4; k++) {
                    unsigned id = ids[k];
                    if (id == prev) continue;                 // spatial dedup
                    prev = id;
                    unsigned wd = id >> 5, m = 1u << (id & 31);
                    if (!(bmp[wd] & m)) {                     // test first
                        unsigned old = atomicOr(&bmp[wd], m);
                        if (!(old & m)) cnt++;                // flipped the bit
                    }
                }
            }
        }
#pragma unroll
        for (int o = 16; o; o >>= 1) cnt += __shfl_down_sync(FULLMASK, cnt, o);
        if (l == 0 && cnt) atomicAdd(&g_cnt[which], cnt);
    }
}

// ---------------- epilogue ----------------
__global__ void final_kernel(float* __restrict__ out) {
    float acc = 0.f;
    for (int b = 0; b < NBATCH; b++) {
        float num = 0.f, den = 0.f;
        for (int c = 0; c < 32; c++) { num += g_pnum[b * 32 + c]; den += g_pden[b * 32 + c]; }
        acc += 1.0f - (num + 1.0f) / (den + 1.0f);
    }
    float nl = (float)(g_cnt[0] - 1);   // count_unique(labels) - 1
    float nt = (float)g_cnt[1];         // count_unique(target_number)
    float pen = sqrtf(nl / nt);
    if (!isfinite(pen)) pen = (float)NBATCH;
    pen = fminf(fmaxf(pen, 1.0f), (float)NBATCH);
    out[0] = (acc / (float)NBATCH) * pen;
}

// ---------------- launch ----------------
extern "C" void kernel_launch(void* const* d_in, const int* in_sizes, int n_in,
                              void* d_out, int out_size) {
    const float* p = (const float*)d_in[0];
    const float* t = (const float*)d_in[1];
    float* out = (float*)d_out;

    init_kernel<<<512, 256>>>();

    dim3 rgrid(32, 16);
    reduce_kernel<<<rgrid, 256>>>(p, t);

    // 25 prop launches x 8 fused iterations = 200.
    // launch 0: fused seed (reads p/t, writes g_buf[1])
    // launches 1..23: standard ping-pong (src = it&1)
    // launch 24: fused scatter+count (reads g_buf[0], no store)
    dim3 pgrid(5, 7, 32);
    prop8_kernel<1><<<pgrid, 512>>>(0, p, t);
    for (int it = 1; it < 24; ++it)
        prop8_kernel<0><<<pgrid, 512>>>(it & 1, p, t);
    prop8_kernel<2><<<pgrid, 512>>>(0, p, t);

    final_kernel<<<1, 1>>>(out);
}